// round 15
// baseline (speedup 1.0000x reference)
#include <cuda_runtime.h>
#include <cuda_bf16.h>
#include <cstdint>

#define LVL   32
#define PINS  131072
#define NNETS 1000000
#define TPER  10.0f

// Per-arc validity (bit0 = arc0 valid, bit1 = arc1 valid).
__device__ unsigned char g_valid[(LVL - 1) * PINS];

static __device__ __forceinline__ void atomicMinFloat(float* addr, float val) {
    if (val >= 0.0f) {
        atomicMin((int*)addr, __float_as_int(val));
    } else {
        atomicMax((unsigned int*)addr, __float_as_uint(val));
    }
}

// ---- preA (s0): valid bits (all rows) + arr[0] ----
__global__ void sta_preA_kernel(const float* __restrict__ delays,
                                const int2*  __restrict__ net,
                                const unsigned int* __restrict__ mask,
                                float* __restrict__ arr) {
    int i = blockIdx.x * blockDim.x + threadIdx.x;
    if (i < (LVL - 1) * PINS) {
        int2 n = __ldg(&net[i]);
        unsigned v0 = (mask[n.x] == 0u) ? 1u : 0u;
        unsigned v1 = (mask[n.y] == 0u) ? 2u : 0u;
        g_valid[i] = (unsigned char)(v0 | v1);
    }
    if (i < PINS) arr[i] = delays[i];
}

// ---- preB (s2): req init + mask re-emit ----
__global__ void sta_preB_kernel(const unsigned int* __restrict__ mask,
                                float* __restrict__ req,
                                float* __restrict__ mask_out,
                                long long mask_out_room) {
    int i = blockIdx.x * blockDim.x + threadIdx.x;
    if (i < LVL * PINS) req[i] = TPER;
    if (i < NNETS && i < mask_out_room) mask_out[i] = mask[i] ? 1.0f : 0.0f;
}

// ---- fwd body: 4 pins/thread, 8 independent gathers ----
static __device__ __forceinline__ float4
fwd_compute4(const float* __restrict__ ap, float4 d, int4 s0, int4 s1, uchar4 vv) {
    float a0 = (vv.x & 1u) ? __ldg(&ap[s0.x]) : 0.0f;
    float a1 = (vv.x & 2u) ? __ldg(&ap[s0.y]) : 0.0f;
    float b0 = (vv.y & 1u) ? __ldg(&ap[s0.z]) : 0.0f;
    float b1 = (vv.y & 2u) ? __ldg(&ap[s0.w]) : 0.0f;
    float c0 = (vv.z & 1u) ? __ldg(&ap[s1.x]) : 0.0f;
    float c1 = (vv.z & 2u) ? __ldg(&ap[s1.y]) : 0.0f;
    float e0 = (vv.w & 1u) ? __ldg(&ap[s1.z]) : 0.0f;
    float e1 = (vv.w & 2u) ? __ldg(&ap[s1.w]) : 0.0f;

    float4 m;
    m.x = d.x;
    if (vv.x & 1u) m.x = fmaxf(m.x, a0 + d.x);
    if (vv.x & 2u) m.x = fmaxf(m.x, a1 + d.x);
    m.y = d.y;
    if (vv.y & 1u) m.y = fmaxf(m.y, b0 + d.y);
    if (vv.y & 2u) m.y = fmaxf(m.y, b1 + d.y);
    m.z = d.z;
    if (vv.z & 1u) m.z = fmaxf(m.z, c0 + d.z);
    if (vv.z & 2u) m.z = fmaxf(m.z, c1 + d.z);
    m.w = d.w;
    if (vv.w & 1u) m.w = fmaxf(m.w, e0 + d.w);
    if (vv.w & 2u) m.w = fmaxf(m.w, e1 + d.w);
    return m;
}

// ---- forward level l: 4 pins/thread, PDL (GDS then trigger) ----
__global__ void sta_fwd_kernel(const float* __restrict__ delays,
                               const int2*  __restrict__ src,
                               float* __restrict__ arr,
                               int l) {
    int t = blockIdx.x * blockDim.x + threadIdx.x;
    if (t >= PINS / 4) return;

    float4 d  = ((const float4*)(delays + l * PINS))[t];
    int4   s0 = ((const int4*)(src + (l - 1) * PINS))[2 * t];
    int4   s1 = ((const int4*)(src + (l - 1) * PINS))[2 * t + 1];
    uchar4 vv = ((const uchar4*)(g_valid + (l - 1) * PINS))[t];

#if __CUDA_ARCH__ >= 900
    cudaGridDependencySynchronize();
    cudaTriggerProgrammaticLaunchCompletion();
#endif

    const float* ap = arr + (l - 1) * PINS;
    float4 m = fwd_compute4(ap, d, s0, s1, vv);
    ((float4*)(arr + l * PINS))[t] = m;
}

// ---- forward level 31 + slack[31] (req[31] == TPER identically) ----
__global__ void sta_fwd_last_kernel(const float* __restrict__ delays,
                                    const int2*  __restrict__ src,
                                    float* __restrict__ arr,
                                    float* __restrict__ slack) {
    const int l = LVL - 1;
    int t = blockIdx.x * blockDim.x + threadIdx.x;
    if (t >= PINS / 4) return;

    float4 d  = ((const float4*)(delays + l * PINS))[t];
    int4   s0 = ((const int4*)(src + (l - 1) * PINS))[2 * t];
    int4   s1 = ((const int4*)(src + (l - 1) * PINS))[2 * t + 1];
    uchar4 vv = ((const uchar4*)(g_valid + (l - 1) * PINS))[t];

#if __CUDA_ARCH__ >= 900
    cudaGridDependencySynchronize();
    cudaTriggerProgrammaticLaunchCompletion();
#endif

    const float* ap = arr + (l - 1) * PINS;
    float4 m = fwd_compute4(ap, d, s0, s1, vv);
    ((float4*)(arr + l * PINS))[t] = m;
    float4 sl;
    sl.x = TPER - m.x; sl.y = TPER - m.y; sl.z = TPER - m.z; sl.w = TPER - m.w;
    ((float4*)(slack + l * PINS))[t] = sl;
}

// ---- backward level l: scatter-min into req[l] (unchanged, hidden) ----
__global__ void sta_bwd_kernel(const float* __restrict__ delays,
                               const int2*  __restrict__ src,
                               float* __restrict__ req,
                               int l) {
    int t = blockIdx.x * blockDim.x + threadIdx.x;
    if (t >= PINS / 2) return;

    const int up = (l + 1) * PINS;
    float2 d1 = ((const float2*)(delays + up))[t];
    int4   s  = ((const int4*)(src + l * PINS))[t];
    uchar2 vv = ((const uchar2*)(g_valid + l * PINS))[t];

#if __CUDA_ARCH__ >= 900
    cudaGridDependencySynchronize();
    cudaTriggerProgrammaticLaunchCompletion();
#endif

    float2 r1 = __ldcg((const float2*)(req + up) + t);
    float c0 = r1.x - d1.x;
    float c1 = r1.y - d1.y;

    float* rl = req + (long long)l * PINS;
    if (vv.x & 1u) atomicMinFloat(rl + s.x, c0);
    if (vv.x & 2u) atomicMinFloat(rl + s.y, c0);
    if (vv.y & 1u) atomicMinFloat(rl + s.z, c1);
    if (vv.y & 2u) atomicMinFloat(rl + s.w, c1);
}

// ---- epilogue: slack for levels 0..30, float4 ----
__global__ void sta_epilogue_kernel(const float* __restrict__ arr,
                                    const float* __restrict__ req,
                                    float* __restrict__ slack) {
    int t = blockIdx.x * blockDim.x + threadIdx.x;
    const int n = (LVL - 1) * PINS / 4;
    if (t >= n) return;
    float4 r = ((const float4*)req)[t];
    float4 a = ((const float4*)arr)[t];
    float4 o;
    o.x = r.x - a.x; o.y = r.y - a.y; o.z = r.z - a.z; o.w = r.w - a.w;
    ((float4*)slack)[t] = o;
}

// ---------------------------------------------------------------------------
template <typename... Args>
static void launch_pdl(cudaStream_t st, dim3 grid, dim3 block, bool pdl,
                       void (*kern)(Args...), Args... args) {
    cudaLaunchConfig_t cfg = {};
    cfg.gridDim = grid;
    cfg.blockDim = block;
    cfg.stream = st;
    cudaLaunchAttribute at[1];
    if (pdl) {
        at[0].id = cudaLaunchAttributeProgrammaticStreamSerialization;
        at[0].val.programmaticStreamSerializationAllowed = 1;
        cfg.attrs = at;
        cfg.numAttrs = 1;
    }
    cudaLaunchKernelEx(&cfg, kern, args...);
}

extern "C" void kernel_launch(void* const* d_in, const int* in_sizes, int n_in,
                              void* d_out, int out_size) {
    const float*        delays = (const float*)d_in[0];
    const int2*         src    = (const int2*)d_in[1];
    const int2*         net    = (const int2*)d_in[2];
    const unsigned int* mask   = (const unsigned int*)d_in[3];

    float* out = (float*)d_out;
    const long long LP = (long long)LVL * PINS;

    float* arr      = out;           // [0,   LP)
    float* req      = out + LP;      // [LP,  2LP)
    float* slack    = out + 2 * LP;  // [2LP, 3LP)
    float* mask_out = out + 3 * LP;  // [3LP, ...)
    long long mask_room = (long long)out_size - 3 * LP;

    cudaStream_t s0 = (cudaStream_t)0;

    // Static handles: created once on the first (pre-capture) call.
    static cudaStream_t s2 = nullptr;
    static cudaEvent_t evFork = nullptr, evA = nullptr, evBwd = nullptr;
    if (!s2) {
        cudaStreamCreateWithFlags(&s2, cudaStreamNonBlocking);
        cudaEventCreateWithFlags(&evFork, cudaEventDisableTiming);
        cudaEventCreateWithFlags(&evA,    cudaEventDisableTiming);
        cudaEventCreateWithFlags(&evBwd,  cudaEventDisableTiming);
    }

    const int T = 128;
    const int blocksQ = (PINS / 4 + T - 1) / T;     // 256 (fwd: 4 pins/thread)
    const int blocksH = (PINS / 2 + T - 1) / T;     // 512 (bwd: 2 pins/thread)

    // fork s2
    cudaEventRecord(evFork, s0);
    cudaStreamWaitEvent(s2, evFork, 0);

    // s0: preA (valid bits + arr[0]) then the entire fwd chain (no mid events)
    {
        int bA = ((LVL - 1) * PINS + 255) / 256;
        sta_preA_kernel<<<bA, 256, 0, s0>>>(delays, net, mask, arr);
        cudaEventRecord(evA, s0);
    }
    for (int l = 1; l < LVL - 1; ++l)
        launch_pdl(s0, dim3(blocksQ), dim3(T), true, sta_fwd_kernel, delays, src, arr, l);
    launch_pdl(s0, dim3(blocksQ), dim3(T), true,
               sta_fwd_last_kernel, delays, src, arr, slack);

    // s2: preB, then bwd chain (needs g_valid -> evA)
    {
        int bB = (int)((LP + 255) / 256);
        sta_preB_kernel<<<bB, 256, 0, s2>>>(mask, req, mask_out, mask_room);
        cudaStreamWaitEvent(s2, evA, 0);
        for (int l = LVL - 2; l >= 0; --l)
            launch_pdl(s2, dim3(blocksH), dim3(T), l != LVL - 2,
                       sta_bwd_kernel, delays, src, req, l);
        cudaEventRecord(evBwd, s2);
    }

    // join at the very end, then epilogue (levels 0..30)
    cudaStreamWaitEvent(s0, evBwd, 0);
    {
        int n = (LVL - 1) * PINS / 4;
        int b = (n + 255) / 256;
        sta_epilogue_kernel<<<b, 256, 0, s0>>>(arr, req, slack);
    }
}

// round 16
// speedup vs baseline: 1.1112x; 1.1112x over previous
#include <cuda_runtime.h>
#include <cuda_bf16.h>
#include <cstdint>

#define LVL   32
#define PINS  131072
#define NNETS 1000000
#define TPER  10.0f

// Per-arc validity (bit0 = arc0 valid, bit1 = arc1 valid).
__device__ unsigned char g_valid[(LVL - 1) * PINS];

static __device__ __forceinline__ void atomicMinFloat(float* addr, float val) {
    if (val >= 0.0f) {
        atomicMin((int*)addr, __float_as_int(val));
    } else {
        atomicMax((unsigned int*)addr, __float_as_uint(val));
    }
}

// ---- preA (s0): valid bits (all rows) + arr[0] ----
__global__ void sta_preA_kernel(const float* __restrict__ delays,
                                const int2*  __restrict__ net,
                                const unsigned int* __restrict__ mask,
                                float* __restrict__ arr) {
    int i = blockIdx.x * blockDim.x + threadIdx.x;
    if (i < (LVL - 1) * PINS) {
        int2 n = __ldg(&net[i]);
        unsigned v0 = (mask[n.x] == 0u) ? 1u : 0u;
        unsigned v1 = (mask[n.y] == 0u) ? 2u : 0u;
        g_valid[i] = (unsigned char)(v0 | v1);
    }
    if (i < PINS) arr[i] = delays[i];
}

// ---- preB (s2): req init + mask re-emit ----
__global__ void sta_preB_kernel(const unsigned int* __restrict__ mask,
                                float* __restrict__ req,
                                float* __restrict__ mask_out,
                                long long mask_out_room) {
    int i = blockIdx.x * blockDim.x + threadIdx.x;
    if (i < LVL * PINS) req[i] = TPER;
    if (i < NNETS && i < mask_out_room) mask_out[i] = mask[i] ? 1.0f : 0.0f;
}

// ---- forward level l: 2 pins/thread, PDL (GDS then trigger) ----
__global__ void sta_fwd_kernel(const float* __restrict__ delays,
                               const int2*  __restrict__ src,
                               float* __restrict__ arr,
                               int l) {
    int t = blockIdx.x * blockDim.x + threadIdx.x;
    if (t >= PINS / 2) return;

    float2 d  = ((const float2*)(delays + l * PINS))[t];
    int4   s  = ((const int4*)(src + (l - 1) * PINS))[t];
    uchar2 vv = ((const uchar2*)(g_valid + (l - 1) * PINS))[t];

#if __CUDA_ARCH__ >= 900
    cudaGridDependencySynchronize();
    cudaTriggerProgrammaticLaunchCompletion();
#endif

    const float* ap = arr + (l - 1) * PINS;
    float a0 = (vv.x & 1u) ? __ldg(&ap[s.x]) : 0.0f;
    float a1 = (vv.x & 2u) ? __ldg(&ap[s.y]) : 0.0f;
    float b0 = (vv.y & 1u) ? __ldg(&ap[s.z]) : 0.0f;
    float b1 = (vv.y & 2u) ? __ldg(&ap[s.w]) : 0.0f;

    float m0 = d.x;
    if (vv.x & 1u) m0 = fmaxf(m0, a0 + d.x);
    if (vv.x & 2u) m0 = fmaxf(m0, a1 + d.x);
    float m1 = d.y;
    if (vv.y & 1u) m1 = fmaxf(m1, b0 + d.y);
    if (vv.y & 2u) m1 = fmaxf(m1, b1 + d.y);

    ((float2*)(arr + l * PINS))[t] = make_float2(m0, m1);
}

// ---- forward level 31 + slack[31] (req[31] == TPER identically) ----
__global__ void sta_fwd_last_kernel(const float* __restrict__ delays,
                                    const int2*  __restrict__ src,
                                    float* __restrict__ arr,
                                    float* __restrict__ slack) {
    const int l = LVL - 1;
    int t = blockIdx.x * blockDim.x + threadIdx.x;
    if (t >= PINS / 2) return;

    float2 d  = ((const float2*)(delays + l * PINS))[t];
    int4   s  = ((const int4*)(src + (l - 1) * PINS))[t];
    uchar2 vv = ((const uchar2*)(g_valid + (l - 1) * PINS))[t];

#if __CUDA_ARCH__ >= 900
    cudaGridDependencySynchronize();
    cudaTriggerProgrammaticLaunchCompletion();
#endif

    const float* ap = arr + (l - 1) * PINS;
    float a0 = (vv.x & 1u) ? __ldg(&ap[s.x]) : 0.0f;
    float a1 = (vv.x & 2u) ? __ldg(&ap[s.y]) : 0.0f;
    float b0 = (vv.y & 1u) ? __ldg(&ap[s.z]) : 0.0f;
    float b1 = (vv.y & 2u) ? __ldg(&ap[s.w]) : 0.0f;

    float m0 = d.x;
    if (vv.x & 1u) m0 = fmaxf(m0, a0 + d.x);
    if (vv.x & 2u) m0 = fmaxf(m0, a1 + d.x);
    float m1 = d.y;
    if (vv.y & 1u) m1 = fmaxf(m1, b0 + d.y);
    if (vv.y & 2u) m1 = fmaxf(m1, b1 + d.y);

    ((float2*)(arr + l * PINS))[t] = make_float2(m0, m1);
    ((float2*)(slack + l * PINS))[t] = make_float2(TPER - m0, TPER - m1);
}

// ---- backward level l: scatter-min into req[l] ----
__global__ void sta_bwd_kernel(const float* __restrict__ delays,
                               const int2*  __restrict__ src,
                               float* __restrict__ req,
                               int l) {
    int t = blockIdx.x * blockDim.x + threadIdx.x;
    if (t >= PINS / 2) return;

    const int up = (l + 1) * PINS;
    float2 d1 = ((const float2*)(delays + up))[t];
    int4   s  = ((const int4*)(src + l * PINS))[t];
    uchar2 vv = ((const uchar2*)(g_valid + l * PINS))[t];

#if __CUDA_ARCH__ >= 900
    cudaGridDependencySynchronize();
    cudaTriggerProgrammaticLaunchCompletion();
#endif

    float2 r1 = __ldcg((const float2*)(req + up) + t);
    float c0 = r1.x - d1.x;
    float c1 = r1.y - d1.y;

    float* rl = req + (long long)l * PINS;
    if (vv.x & 1u) atomicMinFloat(rl + s.x, c0);
    if (vv.x & 2u) atomicMinFloat(rl + s.y, c0);
    if (vv.y & 1u) atomicMinFloat(rl + s.z, c1);
    if (vv.y & 2u) atomicMinFloat(rl + s.w, c1);
}

// ---- epilogue: slack for levels 0..30, float4 ----
__global__ void sta_epilogue_kernel(const float* __restrict__ arr,
                                    const float* __restrict__ req,
                                    float* __restrict__ slack) {
    int t = blockIdx.x * blockDim.x + threadIdx.x;
    const int n = (LVL - 1) * PINS / 4;
    if (t >= n) return;
    float4 r = ((const float4*)req)[t];
    float4 a = ((const float4*)arr)[t];
    float4 o;
    o.x = r.x - a.x; o.y = r.y - a.y; o.z = r.z - a.z; o.w = r.w - a.w;
    ((float4*)slack)[t] = o;
}

// ---------------------------------------------------------------------------
template <typename... Args>
static void launch_pdl(cudaStream_t st, dim3 grid, dim3 block, bool pdl,
                       void (*kern)(Args...), Args... args) {
    cudaLaunchConfig_t cfg = {};
    cfg.gridDim = grid;
    cfg.blockDim = block;
    cfg.stream = st;
    cudaLaunchAttribute at[1];
    if (pdl) {
        at[0].id = cudaLaunchAttributeProgrammaticStreamSerialization;
        at[0].val.programmaticStreamSerializationAllowed = 1;
        cfg.attrs = at;
        cfg.numAttrs = 1;
    }
    cudaLaunchKernelEx(&cfg, kern, args...);
}

extern "C" void kernel_launch(void* const* d_in, const int* in_sizes, int n_in,
                              void* d_out, int out_size) {
    const float*        delays = (const float*)d_in[0];
    const int2*         src    = (const int2*)d_in[1];
    const int2*         net    = (const int2*)d_in[2];
    const unsigned int* mask   = (const unsigned int*)d_in[3];

    float* out = (float*)d_out;
    const long long LP = (long long)LVL * PINS;

    float* arr      = out;           // [0,   LP)
    float* req      = out + LP;      // [LP,  2LP)
    float* slack    = out + 2 * LP;  // [2LP, 3LP)
    float* mask_out = out + 3 * LP;  // [3LP, ...)
    long long mask_room = (long long)out_size - 3 * LP;

    cudaStream_t s0 = (cudaStream_t)0;

    // Static handles: created once on the first (pre-capture) call.
    static cudaStream_t s2 = nullptr;
    static cudaEvent_t evFork = nullptr, evA = nullptr, evBwd = nullptr;
    if (!s2) {
        cudaStreamCreateWithFlags(&s2, cudaStreamNonBlocking);
        cudaEventCreateWithFlags(&evFork, cudaEventDisableTiming);
        cudaEventCreateWithFlags(&evA,    cudaEventDisableTiming);
        cudaEventCreateWithFlags(&evBwd,  cudaEventDisableTiming);
    }

    const int T = 128;
    const int blocksH = (PINS / 2 + T - 1) / T;     // 512

    // fork s2
    cudaEventRecord(evFork, s0);
    cudaStreamWaitEvent(s2, evFork, 0);

    // s0: preA (valid bits + arr[0]) then the entire fwd chain (no mid events)
    {
        int bA = ((LVL - 1) * PINS + 255) / 256;
        sta_preA_kernel<<<bA, 256, 0, s0>>>(delays, net, mask, arr);
        cudaEventRecord(evA, s0);
    }
    for (int l = 1; l < LVL - 1; ++l)
        launch_pdl(s0, dim3(blocksH), dim3(T), true, sta_fwd_kernel, delays, src, arr, l);
    launch_pdl(s0, dim3(blocksH), dim3(T), true,
               sta_fwd_last_kernel, delays, src, arr, slack);

    // s2: preB, then bwd chain (needs g_valid -> evA)
    {
        int bB = (int)((LP + 255) / 256);
        sta_preB_kernel<<<bB, 256, 0, s2>>>(mask, req, mask_out, mask_room);
        cudaStreamWaitEvent(s2, evA, 0);
        for (int l = LVL - 2; l >= 0; --l)
            launch_pdl(s2, dim3(blocksH), dim3(T), l != LVL - 2,
                       sta_bwd_kernel, delays, src, req, l);
        cudaEventRecord(evBwd, s2);
    }

    // join at the very end, then epilogue (levels 0..30)
    cudaStreamWaitEvent(s0, evBwd, 0);
    {
        int n = (LVL - 1) * PINS / 4;
        int b = (n + 255) / 256;
        sta_epilogue_kernel<<<b, 256, 0, s0>>>(arr, req, slack);
    }
}